// round 1
// baseline (speedup 1.0000x reference)
#include <cuda_runtime.h>
#include <cuda_bf16.h>

#define B_  4
#define S_  2048
#define D_  1024
#define H_  16
#define DH_ 64
#define NEG_INF_ -1000000000.0f

// ---------------- scratch (allocation-free rule: __device__ globals) ----------------
__device__ float g_q[(size_t)B_ * H_ * S_ * DH_];     // 32 MB
__device__ float g_k[(size_t)B_ * H_ * S_ * DH_];     // 32 MB
__device__ float g_v[(size_t)B_ * H_ * S_ * DH_];     // 32 MB
__device__ float g_ctx[(size_t)B_ * S_ * D_];         // 32 MB
__device__ float g_s[(size_t)B_ * H_ * S_ * S_];      // 1 GiB scores/probs
__device__ unsigned char g_m8[B_ * S_];               // normalized mask

// ---------------- mask dtype sniff + normalize ----------------
// padding_mask is a bool array in the reference; harness dtype is unknown
// (int8/bool, int32, float32, bf16 all possible). Scan only the first
// B_*S_ bytes (the minimum possible buffer size) to classify, then normalize.
__global__ void mask_prep_kernel(const unsigned char* __restrict__ mraw) {
    __shared__ int flags[3];  // [0]=f32 marker, [1]=any 0x3f (bf16), [2]=nonzero at i%4!=0
    int tid = threadIdx.x;
    if (tid < 3) flags[tid] = 0;
    __syncthreads();
    for (int i = tid; i < B_ * S_; i += blockDim.x) {
        unsigned char b = mraw[i];
        if (b == 0x3f) {
            if ((i & 3) == 3) atomicOr(&flags[0], 1);
            atomicOr(&flags[1], 1);
        } else if (b != 0 && (i & 3) != 0) {
            atomicOr(&flags[2], 1);
        }
    }
    __syncthreads();
    int dtype;
    if (flags[0])      dtype = 2;  // float32
    else if (flags[1]) dtype = 3;  // bf16
    else if (flags[2]) dtype = 0;  // int8/bool
    else               dtype = 1;  // int32
    for (int i = tid; i < B_ * S_; i += blockDim.x) {
        int v;
        if (dtype == 0)      v = (mraw[i] != 0);
        else if (dtype == 1) v = (((const int*)mraw)[i] != 0);
        else if (dtype == 2) v = (((const float*)mraw)[i] != 0.0f);
        else                 v = (((const unsigned short*)mraw)[i] != 0);
        g_m8[i] = (unsigned char)v;
    }
}

// ---------------- fused QKV projection: X[8192,1024] @ W[1024,1024] + b ----------------
// 128x128 tile, BK=16, 256 threads, 8x8 per thread. blockIdx.z selects Q/K/V.
// Output layout: [B, H, S, DH]
__global__ __launch_bounds__(256) void qkv_kernel(
    const float* __restrict__ X,
    const float* __restrict__ Wq, const float* __restrict__ bq,
    const float* __restrict__ Wk, const float* __restrict__ bk,
    const float* __restrict__ Wv, const float* __restrict__ bv)
{
    const float* W; const float* bias; float* out;
    if (blockIdx.z == 0)      { W = Wq; bias = bq; out = g_q; }
    else if (blockIdx.z == 1) { W = Wk; bias = bk; out = g_k; }
    else                      { W = Wv; bias = bv; out = g_v; }

    __shared__ __align__(16) float As[16][128];
    __shared__ __align__(16) float Bs[16][128];
    int tid = threadIdx.x;
    int ty = tid >> 4, tx = tid & 15;
    int m0 = blockIdx.y * 128, n0 = blockIdx.x * 128;
    float acc[8][8] = {};

    for (int k0 = 0; k0 < D_; k0 += 16) {
        #pragma unroll
        for (int i = 0; i < 2; i++) {
            int idx = tid * 2 + i;
            int ar = idx >> 2, aq = (idx & 3) * 4;
            float4 av = *(const float4*)&X[(size_t)(m0 + ar) * D_ + k0 + aq];
            As[aq + 0][ar] = av.x; As[aq + 1][ar] = av.y;
            As[aq + 2][ar] = av.z; As[aq + 3][ar] = av.w;
            int br = idx >> 5, bc = (idx & 31) * 4;
            *(float4*)&Bs[br][bc] = *(const float4*)&W[(size_t)(k0 + br) * D_ + n0 + bc];
        }
        __syncthreads();
        #pragma unroll
        for (int k = 0; k < 16; k++) {
            float a[8], b[8];
            *(float4*)(a)     = *(float4*)&As[k][ty * 8];
            *(float4*)(a + 4) = *(float4*)&As[k][ty * 8 + 4];
            *(float4*)(b)     = *(float4*)&Bs[k][tx * 8];
            *(float4*)(b + 4) = *(float4*)&Bs[k][tx * 8 + 4];
            #pragma unroll
            for (int i = 0; i < 8; i++)
                #pragma unroll
                for (int j = 0; j < 8; j++)
                    acc[i][j] += a[i] * b[j];
        }
        __syncthreads();
    }

    #pragma unroll
    for (int i = 0; i < 8; i++) {
        int m = m0 + ty * 8 + i;
        int b = m >> 11, s = m & (S_ - 1);
        #pragma unroll
        for (int j = 0; j < 8; j++) {
            int n = n0 + tx * 8 + j;
            int h = n >> 6, d = n & 63;
            out[(((size_t)(b * H_ + h)) * S_ + s) * DH_ + d] = acc[i][j] + bias[n];
        }
    }
}

// ---------------- scores: S = Q @ K^T per (b,h), masked ----------------
// grid: (S/128, S/128, B*H). 128x128 tile, K=64 (BK=16).
__global__ __launch_bounds__(256) void scores_kernel() {
    int bh = blockIdx.z;
    int b = bh >> 4;
    const float* Q = g_q + (size_t)bh * S_ * DH_;
    const float* K = g_k + (size_t)bh * S_ * DH_;
    float* Sout = g_s + (size_t)bh * S_ * S_;
    int m0 = blockIdx.y * 128, n0 = blockIdx.x * 128;

    __shared__ __align__(16) float As[16][128];
    __shared__ __align__(16) float Bs[16][128];
    int tid = threadIdx.x;
    int ty = tid >> 4, tx = tid & 15;
    float acc[8][8] = {};

    for (int k0 = 0; k0 < DH_; k0 += 16) {
        #pragma unroll
        for (int i = 0; i < 2; i++) {
            int idx = tid * 2 + i;
            int r = idx >> 2, q4 = (idx & 3) * 4;
            float4 av = *(const float4*)&Q[(size_t)(m0 + r) * DH_ + k0 + q4];
            As[q4 + 0][r] = av.x; As[q4 + 1][r] = av.y;
            As[q4 + 2][r] = av.z; As[q4 + 3][r] = av.w;
            float4 bv = *(const float4*)&K[(size_t)(n0 + r) * DH_ + k0 + q4];
            Bs[q4 + 0][r] = bv.x; Bs[q4 + 1][r] = bv.y;
            Bs[q4 + 2][r] = bv.z; Bs[q4 + 3][r] = bv.w;
        }
        __syncthreads();
        #pragma unroll
        for (int k = 0; k < 16; k++) {
            float a[8], bb[8];
            *(float4*)(a)      = *(float4*)&As[k][ty * 8];
            *(float4*)(a + 4)  = *(float4*)&As[k][ty * 8 + 4];
            *(float4*)(bb)     = *(float4*)&Bs[k][tx * 8];
            *(float4*)(bb + 4) = *(float4*)&Bs[k][tx * 8 + 4];
            #pragma unroll
            for (int i = 0; i < 8; i++)
                #pragma unroll
                for (int j = 0; j < 8; j++)
                    acc[i][j] += a[i] * bb[j];
        }
        __syncthreads();
    }

    unsigned char km[8];
    #pragma unroll
    for (int j = 0; j < 8; j++) km[j] = g_m8[b * S_ + n0 + tx * 8 + j];

    #pragma unroll
    for (int i = 0; i < 8; i++) {
        size_t off = (size_t)(m0 + ty * 8 + i) * S_;
        #pragma unroll
        for (int j = 0; j < 8; j++) {
            int n = n0 + tx * 8 + j;
            Sout[off + n] = km[j] ? acc[i][j] : NEG_INF_;
        }
    }
}

// ---------------- in-place row softmax over 2048 cols ----------------
__global__ __launch_bounds__(256) void softmax_kernel() {
    float* p = g_s + (size_t)blockIdx.x * S_;
    __shared__ float red[16];
    int tid = threadIdx.x;
    float v[8];
    float vmax = -3.4e38f;
    #pragma unroll
    for (int j = 0; j < 8; j++) {
        v[j] = p[tid + j * 256];
        vmax = fmaxf(vmax, v[j]);
    }
    #pragma unroll
    for (int o = 16; o; o >>= 1) vmax = fmaxf(vmax, __shfl_xor_sync(0xffffffffu, vmax, o));
    if ((tid & 31) == 0) red[tid >> 5] = vmax;
    __syncthreads();
    vmax = red[0];
    #pragma unroll
    for (int j = 1; j < 8; j++) vmax = fmaxf(vmax, red[j]);

    float sum = 0.0f;
    #pragma unroll
    for (int j = 0; j < 8; j++) {
        v[j] = __expf(v[j] - vmax);
        sum += v[j];
    }
    #pragma unroll
    for (int o = 16; o; o >>= 1) sum += __shfl_xor_sync(0xffffffffu, sum, o);
    if ((tid & 31) == 0) red[8 + (tid >> 5)] = sum;
    __syncthreads();
    sum = red[8];
    #pragma unroll
    for (int j = 1; j < 8; j++) sum += red[8 + j];
    float inv = 1.0f / sum;
    #pragma unroll
    for (int j = 0; j < 8; j++) p[tid + j * 256] = v[j] * inv;
}

// ---------------- ctx = P @ V per (b,h), query-masked, layout [B,S,D] ----------------
// grid: (S/128, B*H). 128x64 tile, BK=16, 256 threads, 8x4 per thread.
__global__ __launch_bounds__(256) void ctx_kernel() {
    int bh = blockIdx.y;
    int b = bh >> 4, h = bh & 15;
    const float* P = g_s + (size_t)bh * S_ * S_;
    const float* V = g_v + (size_t)bh * S_ * DH_;
    int m0 = blockIdx.x * 128;

    __shared__ __align__(16) float As[16][128];
    __shared__ __align__(16) float Bs[16][64];
    int tid = threadIdx.x;
    int ty = tid >> 4, tx = tid & 15;
    float acc[8][4] = {};

    for (int k0 = 0; k0 < S_; k0 += 16) {
        #pragma unroll
        for (int i = 0; i < 2; i++) {
            int idx = tid * 2 + i;
            int r = idx >> 2, q4 = (idx & 3) * 4;
            float4 av = *(const float4*)&P[(size_t)(m0 + r) * S_ + k0 + q4];
            As[q4 + 0][r] = av.x; As[q4 + 1][r] = av.y;
            As[q4 + 2][r] = av.z; As[q4 + 3][r] = av.w;
        }
        {
            int r = tid >> 4, c4 = (tid & 15) * 4;
            *(float4*)&Bs[r][c4] = *(const float4*)&V[(size_t)(k0 + r) * DH_ + c4];
        }
        __syncthreads();
        #pragma unroll
        for (int k = 0; k < 16; k++) {
            float a[8], bb[4];
            *(float4*)(a)     = *(float4*)&As[k][ty * 8];
            *(float4*)(a + 4) = *(float4*)&As[k][ty * 8 + 4];
            *(float4*)(bb)    = *(float4*)&Bs[k][tx * 4];
            #pragma unroll
            for (int i = 0; i < 8; i++)
                #pragma unroll
                for (int j = 0; j < 4; j++)
                    acc[i][j] += a[i] * bb[j];
        }
        __syncthreads();
    }

    #pragma unroll
    for (int i = 0; i < 8; i++) {
        int m = m0 + ty * 8 + i;
        float qm = g_m8[b * S_ + m] ? 1.0f : 0.0f;
        float4 o;
        o.x = acc[i][0] * qm; o.y = acc[i][1] * qm;
        o.z = acc[i][2] * qm; o.w = acc[i][3] * qm;
        *(float4*)&g_ctx[((size_t)b * S_ + m) * D_ + h * DH_ + tx * 4] = o;
    }
}

// ---------------- output projection: ctx[8192,1024] @ Wo + bo -> d_out ----------------
__global__ __launch_bounds__(256) void oproj_kernel(
    const float* __restrict__ W, const float* __restrict__ bias, float* __restrict__ out)
{
    __shared__ __align__(16) float As[16][128];
    __shared__ __align__(16) float Bs[16][128];
    int tid = threadIdx.x;
    int ty = tid >> 4, tx = tid & 15;
    int m0 = blockIdx.y * 128, n0 = blockIdx.x * 128;
    float acc[8][8] = {};

    for (int k0 = 0; k0 < D_; k0 += 16) {
        #pragma unroll
        for (int i = 0; i < 2; i++) {
            int idx = tid * 2 + i;
            int ar = idx >> 2, aq = (idx & 3) * 4;
            float4 av = *(const float4*)&g_ctx[(size_t)(m0 + ar) * D_ + k0 + aq];
            As[aq + 0][ar] = av.x; As[aq + 1][ar] = av.y;
            As[aq + 2][ar] = av.z; As[aq + 3][ar] = av.w;
            int br = idx >> 5, bc = (idx & 31) * 4;
            *(float4*)&Bs[br][bc] = *(const float4*)&W[(size_t)(k0 + br) * D_ + n0 + bc];
        }
        __syncthreads();
        #pragma unroll
        for (int k = 0; k < 16; k++) {
            float a[8], b[8];
            *(float4*)(a)     = *(float4*)&As[k][ty * 8];
            *(float4*)(a + 4) = *(float4*)&As[k][ty * 8 + 4];
            *(float4*)(b)     = *(float4*)&Bs[k][tx * 8];
            *(float4*)(b + 4) = *(float4*)&Bs[k][tx * 8 + 4];
            #pragma unroll
            for (int i = 0; i < 8; i++)
                #pragma unroll
                for (int j = 0; j < 8; j++)
                    acc[i][j] += a[i] * b[j];
        }
        __syncthreads();
    }

    #pragma unroll
    for (int i = 0; i < 8; i++) {
        int m = m0 + ty * 8 + i;
        #pragma unroll
        for (int j = 0; j < 8; j++) {
            int n = n0 + tx * 8 + j;
            out[(size_t)m * D_ + n] = acc[i][j] + bias[n];
        }
    }
}

// ---------------- launch ----------------
extern "C" void kernel_launch(void* const* d_in, const int* in_sizes, int n_in,
                              void* d_out, int out_size) {
    (void)in_sizes; (void)n_in; (void)out_size;
    const float* X  = (const float*)d_in[0];
    const unsigned char* mask = (const unsigned char*)d_in[1];
    const float* Wq = (const float*)d_in[2];
    const float* bq = (const float*)d_in[3];
    const float* Wk = (const float*)d_in[4];
    const float* bk = (const float*)d_in[5];
    const float* Wv = (const float*)d_in[6];
    const float* bv = (const float*)d_in[7];
    const float* Wo = (const float*)d_in[8];
    const float* bo = (const float*)d_in[9];
    float* out = (float*)d_out;

    mask_prep_kernel<<<1, 256>>>(mask);
    qkv_kernel<<<dim3(D_ / 128, (B_ * S_) / 128, 3), 256>>>(X, Wq, bq, Wk, bk, Wv, bv);
    scores_kernel<<<dim3(S_ / 128, S_ / 128, B_ * H_), 256>>>();
    softmax_kernel<<<B_ * H_ * S_, 256>>>();
    ctx_kernel<<<dim3(S_ / 128, B_ * H_), 256>>>();
    oproj_kernel<<<dim3(D_ / 128, (B_ * S_) / 128), 256>>>(Wo, bo, out);
}

// round 6
// speedup vs baseline: 1.2505x; 1.2505x over previous
#include <cuda_runtime.h>
#include <cuda_bf16.h>
#include <cstdint>

#define B_  4
#define S_  2048
#define D_  1024
#define H_  16
#define DH_ 64
#define NEG_INF_ -1000000000.0f
#define M_TOT (B_ * S_)   // 8192

// ---------------- scratch (__device__ globals; no allocation allowed) ----------------
__device__ float g_q[(size_t)B_ * H_ * S_ * DH_];
__device__ float g_k[(size_t)B_ * H_ * S_ * DH_];
__device__ float g_v[(size_t)B_ * H_ * S_ * DH_];
__device__ float g_ctx[(size_t)B_ * S_ * D_];
__device__ float g_s[(size_t)B_ * H_ * S_ * S_];      // 1 GiB scores/probs
__device__ unsigned char g_m8[B_ * S_];

__device__ __nv_bfloat16 g_xhi[(size_t)M_TOT * D_];
__device__ __nv_bfloat16 g_xlo[(size_t)M_TOT * D_];
__device__ __nv_bfloat16 g_chi[(size_t)M_TOT * D_];
__device__ __nv_bfloat16 g_clo[(size_t)M_TOT * D_];
__device__ __nv_bfloat16 g_wt_hi[(size_t)4096 * D_];  // W^T, rows: [Wq|Wk|Wv|Wo]
__device__ __nv_bfloat16 g_wt_lo[(size_t)4096 * D_];
__device__ float g_bias[4096];

// ---------------- PTX helpers (base-ISA only: sm_80+ features) ----------------
__device__ __forceinline__ uint32_t smem_u32(const void* p) {
    uint32_t a;
    asm("{ .reg .u64 t; cvta.to.shared.u64 t, %1; cvt.u32.u64 %0, t; }" : "=r"(a) : "l"(p));
    return a;
}
__device__ __forceinline__ void cpasync16(uint32_t saddr, const void* gaddr) {
    asm volatile("cp.async.cg.shared.global [%0], [%1], 16;" :: "r"(saddr), "l"(gaddr));
}
__device__ __forceinline__ void cpasync_commit() {
    asm volatile("cp.async.commit_group;" ::: "memory");
}
__device__ __forceinline__ void ldmx4(uint32_t addr, uint32_t* r) {
    asm volatile("ldmatrix.sync.aligned.m8n8.x4.shared.b16 {%0,%1,%2,%3}, [%4];"
                 : "=r"(r[0]), "=r"(r[1]), "=r"(r[2]), "=r"(r[3]) : "r"(addr));
}
__device__ __forceinline__ void mma_bf16(float* d, const uint32_t* a, uint32_t b0, uint32_t b1) {
    asm volatile(
        "mma.sync.aligned.m16n8k16.row.col.f32.bf16.bf16.f32 "
        "{%0,%1,%2,%3}, {%4,%5,%6,%7}, {%8,%9}, {%0,%1,%2,%3};"
        : "+f"(d[0]), "+f"(d[1]), "+f"(d[2]), "+f"(d[3])
        : "r"(a[0]), "r"(a[1]), "r"(a[2]), "r"(a[3]), "r"(b0), "r"(b1));
}

// ---------------- mask dtype sniff + normalize ----------------
__global__ void mask_prep_kernel(const unsigned char* __restrict__ mraw) {
    __shared__ int flags[3];
    int tid = threadIdx.x;
    if (tid < 3) flags[tid] = 0;
    __syncthreads();
    for (int i = tid; i < B_ * S_; i += blockDim.x) {
        unsigned char b = mraw[i];
        if (b == 0x3f) {
            if ((i & 3) == 3) atomicOr(&flags[0], 1);
            atomicOr(&flags[1], 1);
        } else if (b != 0 && (i & 3) != 0) {
            atomicOr(&flags[2], 1);
        }
    }
    __syncthreads();
    int dtype;
    if (flags[0])      dtype = 2;
    else if (flags[1]) dtype = 3;
    else if (flags[2]) dtype = 0;
    else               dtype = 1;
    for (int i = tid; i < B_ * S_; i += blockDim.x) {
        int v;
        if (dtype == 0)      v = (mraw[i] != 0);
        else if (dtype == 1) v = (((const int*)mraw)[i] != 0);
        else if (dtype == 2) v = (((const float*)mraw)[i] != 0.0f);
        else                 v = (((const unsigned short*)mraw)[i] != 0);
        g_m8[i] = (unsigned char)v;
    }
}

// ---------------- fp32 -> bf16 hi/lo split (elementwise) ----------------
__global__ __launch_bounds__(256) void split_kernel(
    const float* __restrict__ x, __nv_bfloat16* __restrict__ hi,
    __nv_bfloat16* __restrict__ lo, int n4)
{
    int i = blockIdx.x * 256 + threadIdx.x;
    if (i >= n4) return;
    float4 v = ((const float4*)x)[i];
    float vv[4] = {v.x, v.y, v.z, v.w};
    #pragma unroll
    for (int j = 0; j < 4; j++) {
        __nv_bfloat16 h = __float2bfloat16(vv[j]);
        __nv_bfloat16 l = __float2bfloat16(vv[j] - __bfloat162float(h));
        hi[(size_t)i * 4 + j] = h;
        lo[(size_t)i * 4 + j] = l;
    }
}

// ---------------- weight transpose + split: g_wt[n][k] = W[k][n] ----------------
__global__ void wsplit_kernel(const float* __restrict__ Wq, const float* __restrict__ Wk,
                              const float* __restrict__ Wv, const float* __restrict__ Wo)
{
    __shared__ float t[32][33];
    int mat = blockIdx.z;
    const float* W = (mat == 0) ? Wq : (mat == 1) ? Wk : (mat == 2) ? Wv : Wo;
    int k0 = blockIdx.y * 32, n0 = blockIdx.x * 32;
    int tx = threadIdx.x, ty = threadIdx.y;  // 32 x 8
    for (int r = ty; r < 32; r += 8)
        t[r][tx] = W[(size_t)(k0 + r) * D_ + n0 + tx];
    __syncthreads();
    for (int r = ty; r < 32; r += 8) {
        float v = t[tx][r];  // = W[k0+tx][n0+r]
        __nv_bfloat16 h = __float2bfloat16(v);
        __nv_bfloat16 l = __float2bfloat16(v - __bfloat162float(h));
        size_t o = (size_t)(mat * 1024 + n0 + r) * D_ + k0 + tx;
        g_wt_hi[o] = h;
        g_wt_lo[o] = l;
    }
}

__global__ void bias_kernel(const float* __restrict__ bq, const float* __restrict__ bk,
                            const float* __restrict__ bv, const float* __restrict__ bo)
{
    int i = blockIdx.x * 256 + threadIdx.x;
    if (i >= 4096) return;
    float v;
    if (i < 1024)      v = bq[i];
    else if (i < 2048) v = bk[i - 1024];
    else if (i < 3072) v = bv[i - 2048];
    else               v = bo[i - 3072];
    g_bias[i] = v;
}

// ---------------- mma.sync bf16x3 GEMM: C[m][n] = sum_k A[m][k]*Wt[n][k] + bias ----------------
// CTA tile 128x128, BK=32, 256 thr = 8 warps (4m x 2n), warp tile 32x64.
// cp.async double buffer; stride-40(bf16) rows for conflict-free ldmatrix.
#define MMROW 40                         // bf16 units per smem row (80 B)
#define TILEB (128 * MMROW * 2)          // 10240 B per 128x32 bf16 tile
#define STAGEB (4 * TILEB)               // Ah, Al, Bh, Bl = 40960 B
#define MM_SMEM (2 * STAGEB)             // 81920 B

__global__ __launch_bounds__(256, 1) void mm_bf16x3(
    const __nv_bfloat16* __restrict__ Ahi, const __nv_bfloat16* __restrict__ Alo,
    int n_base_global, int mode, float* __restrict__ out_plain)
{
    extern __shared__ __align__(16) unsigned char dsm[];
    const int tid = threadIdx.x, lane = tid & 31, wid = tid >> 5;
    const int wm = wid >> 1, wn = wid & 1;     // 4 x 2 warp grid
    const int m0 = blockIdx.y * 128;
    const int nb = n_base_global + blockIdx.x * 128;
    const uint32_t sbase = smem_u32(dsm);

    const __nv_bfloat16* srcs[4];
    srcs[0] = Ahi + (size_t)m0 * D_;
    srcs[1] = Alo + (size_t)m0 * D_;
    srcs[2] = g_wt_hi + (size_t)nb * D_;
    srcs[3] = g_wt_lo + (size_t)nb * D_;

    float d[2][8][4] = {};

    const int NITER = D_ / 32;  // 32

    // issue one stage of cp.async loads (128x32 bf16 x 4 tiles)
    auto load_stage = [&](int iter, int buf) {
        uint32_t sb = sbase + (uint32_t)buf * STAGEB;
        int k0 = iter * 32;
        #pragma unroll
        for (int t4 = 0; t4 < 4; t4++) {
            const __nv_bfloat16* src = srcs[t4] + k0;
            uint32_t tb = sb + (uint32_t)t4 * TILEB;
            #pragma unroll
            for (int u = 0; u < 2; u++) {
                int c = tid * 2 + u;            // 0..511
                int row = c >> 2, cg = c & 3;   // cg: 16B chunk (8 bf16)
                cpasync16(tb + (uint32_t)(row * 80 + cg * 16),
                          src + (size_t)row * D_ + cg * 8);
            }
        }
        cpasync_commit();
    };

    load_stage(0, 0);

    for (int i = 0; i < NITER; i++) {
        if (i + 1 < NITER) {
            load_stage(i + 1, (i + 1) & 1);
            asm volatile("cp.async.wait_group 1;" ::: "memory");
        } else {
            asm volatile("cp.async.wait_group 0;" ::: "memory");
        }
        __syncthreads();

        uint32_t sb = sbase + (uint32_t)(i & 1) * STAGEB;
        uint32_t aH = sb, aL = sb + TILEB, bH = sb + 2 * TILEB, bL = sb + 3 * TILEB;

        #pragma unroll
        for (int ks = 0; ks < 2; ks++) {
            // A fragments (hi & lo), one x4 per 16-row frag
            uint32_t ah[2][4], al[2][4];
            #pragma unroll
            for (int mf = 0; mf < 2; mf++) {
                uint32_t off = (uint32_t)((wm * 32 + mf * 16 + (lane & 15)) * 80 +
                                          (ks * 16 + ((lane >> 4) << 3)) * 2);
                ldmx4(aH + off, ah[mf]);
                ldmx4(aL + off, al[mf]);
            }
            // B fragments: each x4 covers two n-frags
            uint32_t bh[4][4], bl[4][4];
            #pragma unroll
            for (int np = 0; np < 4; np++) {
                uint32_t off = (uint32_t)((wn * 64 + np * 16 + ((lane >> 4) << 3) + (lane & 7)) * 80 +
                                          (ks * 16 + ((lane >> 3) & 1) * 8) * 2);
                ldmx4(bH + off, bh[np]);
                ldmx4(bL + off, bl[np]);
            }
            #pragma unroll
            for (int mf = 0; mf < 2; mf++)
                #pragma unroll
                for (int np = 0; np < 4; np++) {
                    #pragma unroll
                    for (int half = 0; half < 2; half++) {
                        int nf = np * 2 + half;
                        uint32_t b0h = bh[np][half * 2], b1h = bh[np][half * 2 + 1];
                        uint32_t b0l = bl[np][half * 2], b1l = bl[np][half * 2 + 1];
                        mma_bf16(d[mf][nf], ah[mf], b0h, b1h);   // hi*hi
                        mma_bf16(d[mf][nf], al[mf], b0h, b1h);   // lo*hi
                        mma_bf16(d[mf][nf], ah[mf], b0l, b1l);   // hi*lo
                    }
                }
        }
        __syncthreads();
    }

    // epilogue: direct global stores with bias
    #pragma unroll
    for (int mf = 0; mf < 2; mf++) {
        #pragma unroll
        for (int nf = 0; nf < 8; nf++) {
            int row0 = m0 + wm * 32 + mf * 16 + (lane >> 2);
            int colg = nb + wn * 64 + nf * 8 + (lane & 3) * 2;
            float bia0 = g_bias[colg], bia1 = g_bias[colg + 1];
            float2 v0 = make_float2(d[mf][nf][0] + bia0, d[mf][nf][1] + bia1);
            float2 v1 = make_float2(d[mf][nf][2] + bia0, d[mf][nf][3] + bia1);
            if (mode == 0) {
                int mat = colg >> 10, col = colg & 1023, h = col >> 6, dd = col & 63;
                float* outp = (mat == 0) ? g_q : (mat == 1) ? g_k : g_v;
                int bi0 = row0 >> 11, s0 = row0 & (S_ - 1);
                *(float2*)&outp[(((size_t)(bi0 * H_ + h)) * S_ + s0) * DH_ + dd] = v0;
                int row1 = row0 + 8;
                int bi1 = row1 >> 11, s1 = row1 & (S_ - 1);
                *(float2*)&outp[(((size_t)(bi1 * H_ + h)) * S_ + s1) * DH_ + dd] = v1;
            } else {
                int n = colg - 3072;
                *(float2*)&out_plain[(size_t)row0 * D_ + n] = v0;
                *(float2*)&out_plain[(size_t)(row0 + 8) * D_ + n] = v1;
            }
        }
    }
}

// ---------------- scores: S = Q @ K^T per (b,h), masked ----------------
__global__ __launch_bounds__(256) void scores_kernel() {
    int bh = blockIdx.z;
    int b = bh >> 4;
    const float* Q = g_q + (size_t)bh * S_ * DH_;
    const float* K = g_k + (size_t)bh * S_ * DH_;
    float* Sout = g_s + (size_t)bh * S_ * S_;
    int m0 = blockIdx.y * 128, n0 = blockIdx.x * 128;

    __shared__ __align__(16) float As[16][128];
    __shared__ __align__(16) float Bs[16][128];
    int tid = threadIdx.x;
    int ty = tid >> 4, tx = tid & 15;
    float acc[8][8] = {};

    for (int k0 = 0; k0 < DH_; k0 += 16) {
        #pragma unroll
        for (int i = 0; i < 2; i++) {
            int idx = tid * 2 + i;
            int r = idx >> 2, q4 = (idx & 3) * 4;
            float4 av = *(const float4*)&Q[(size_t)(m0 + r) * DH_ + k0 + q4];
            As[q4 + 0][r] = av.x; As[q4 + 1][r] = av.y;
            As[q4 + 2][r] = av.z; As[q4 + 3][r] = av.w;
            float4 bv = *(const float4*)&K[(size_t)(n0 + r) * DH_ + k0 + q4];
            Bs[q4 + 0][r] = bv.x; Bs[q4 + 1][r] = bv.y;
            Bs[q4 + 2][r] = bv.z; Bs[q4 + 3][r] = bv.w;
        }
        __syncthreads();
        #pragma unroll
        for (int k = 0; k < 16; k++) {
            float a[8], bb[8];
            *(float4*)(a)      = *(float4*)&As[k][ty * 8];
            *(float4*)(a + 4)  = *(float4*)&As[k][ty * 8 + 4];
            *(float4*)(bb)     = *(float4*)&Bs[k][tx * 8];
            *(float4*)(bb + 4) = *(float4*)&Bs[k][tx * 8 + 4];
            #pragma unroll
            for (int i = 0; i < 8; i++)
                #pragma unroll
                for (int j = 0; j < 8; j++)
                    acc[i][j] += a[i] * bb[j];
        }
        __syncthreads();
    }

    unsigned char km[8];
    #pragma unroll
    for (int j = 0; j < 8; j++) km[j] = g_m8[b * S_ + n0 + tx * 8 + j];

    #pragma unroll
    for (int i = 0; i < 8; i++) {
        size_t off = (size_t)(m0 + ty * 8 + i) * S_;
        #pragma unroll
        for (int j = 0; j < 8; j++) {
            int n = n0 + tx * 8 + j;
            Sout[off + n] = km[j] ? acc[i][j] : NEG_INF_;
        }
    }
}

// ---------------- in-place row softmax ----------------
__global__ __launch_bounds__(256) void softmax_kernel() {
    float* p = g_s + (size_t)blockIdx.x * S_;
    __shared__ float red[16];
    int tid = threadIdx.x;
    float v[8];
    float vmax = -3.4e38f;
    #pragma unroll
    for (int j = 0; j < 8; j++) {
        v[j] = p[tid + j * 256];
        vmax = fmaxf(vmax, v[j]);
    }
    #pragma unroll
    for (int o = 16; o; o >>= 1) vmax = fmaxf(vmax, __shfl_xor_sync(0xffffffffu, vmax, o));
    if ((tid & 31) == 0) red[tid >> 5] = vmax;
    __syncthreads();
    vmax = red[0];
    #pragma unroll
    for (int j = 1; j < 8; j++) vmax = fmaxf(vmax, red[j]);

    float sum = 0.0f;
    #pragma unroll
    for (int j = 0; j < 8; j++) {
        v[j] = __expf(v[j] - vmax);
        sum += v[j];
    }
    #pragma unroll
    for (int o = 16; o; o >>= 1) sum += __shfl_xor_sync(0xffffffffu, sum, o);
    if ((tid & 31) == 0) red[8 + (tid >> 5)] = sum;
    __syncthreads();
    sum = red[8];
    #pragma unroll
    for (int j = 1; j < 8; j++) sum += red[8 + j];
    float inv = 1.0f / sum;
    #pragma unroll
    for (int j = 0; j < 8; j++) p[tid + j * 256] = v[j] * inv;
}

// ---------------- ctx = P @ V per (b,h), query-masked, layout [B,S,D] ----------------
__global__ __launch_bounds__(256) void ctx_kernel() {
    int bh = blockIdx.y;
    int b = bh >> 4, h = bh & 15;
    const float* P = g_s + (size_t)bh * S_ * S_;
    const float* V = g_v + (size_t)bh * S_ * DH_;
    int m0 = blockIdx.x * 128;

    __shared__ __align__(16) float As[16][128];
    __shared__ __align__(16) float Bs[16][64];
    int tid = threadIdx.x;
    int ty = tid >> 4, tx = tid & 15;
    float acc[8][4] = {};

    for (int k0 = 0; k0 < S_; k0 += 16) {
        #pragma unroll
        for (int i = 0; i < 2; i++) {
            int idx = tid * 2 + i;
            int r = idx >> 2, q4 = (idx & 3) * 4;
            float4 av = *(const float4*)&P[(size_t)(m0 + r) * S_ + k0 + q4];
            As[q4 + 0][r] = av.x; As[q4 + 1][r] = av.y;
            As[q4 + 2][r] = av.z; As[q4 + 3][r] = av.w;
        }
        {
            int r = tid >> 4, c4 = (tid & 15) * 4;
            *(float4*)&Bs[r][c4] = *(const float4*)&V[(size_t)(k0 + r) * DH_ + c4];
        }
        __syncthreads();
        #pragma unroll
        for (int k = 0; k < 16; k++) {
            float a[8], bb[4];
            *(float4*)(a)     = *(float4*)&As[k][ty * 8];
            *(float4*)(a + 4) = *(float4*)&As[k][ty * 8 + 4];
            *(float4*)(bb)    = *(float4*)&Bs[k][tx * 4];
            #pragma unroll
            for (int i = 0; i < 8; i++)
                #pragma unroll
                for (int j = 0; j < 4; j++)
                    acc[i][j] += a[i] * bb[j];
        }
        __syncthreads();
    }

    #pragma unroll
    for (int i = 0; i < 8; i++) {
        int m = m0 + ty * 8 + i;
        float qm = g_m8[b * S_ + m] ? 1.0f : 0.0f;
        float4 o;
        o.x = acc[i][0] * qm; o.y = acc[i][1] * qm;
        o.z = acc[i][2] * qm; o.w = acc[i][3] * qm;
        *(float4*)&g_ctx[((size_t)b * S_ + m) * D_ + h * DH_ + tx * 4] = o;
    }
}

// ---------------- launch ----------------
extern "C" void kernel_launch(void* const* d_in, const int* in_sizes, int n_in,
                              void* d_out, int out_size) {
    (void)in_sizes; (void)n_in; (void)out_size;
    const float* X  = (const float*)d_in[0];
    const unsigned char* mask = (const unsigned char*)d_in[1];
    const float* Wq = (const float*)d_in[2];
    const float* bq = (const float*)d_in[3];
    const float* Wk = (const float*)d_in[4];
    const float* bk = (const float*)d_in[5];
    const float* Wv = (const float*)d_in[6];
    const float* bv = (const float*)d_in[7];
    const float* Wo = (const float*)d_in[8];
    const float* bo = (const float*)d_in[9];
    float* out = (float*)d_out;

    cudaFuncSetAttribute(mm_bf16x3, cudaFuncAttributeMaxDynamicSharedMemorySize, MM_SMEM);

    __nv_bfloat16 *xhi, *xlo, *chi, *clo;
    cudaGetSymbolAddress((void**)&xhi, g_xhi);
    cudaGetSymbolAddress((void**)&xlo, g_xlo);
    cudaGetSymbolAddress((void**)&chi, g_chi);
    cudaGetSymbolAddress((void**)&clo, g_clo);
    float* ctxp;
    cudaGetSymbolAddress((void**)&ctxp, g_ctx);

    mask_prep_kernel<<<1, 256>>>(mask);
    wsplit_kernel<<<dim3(32, 32, 4), dim3(32, 8)>>>(Wq, Wk, Wv, Wo);
    bias_kernel<<<16, 256>>>(bq, bk, bv, bo);
    split_kernel<<<(M_TOT * D_ / 4 + 255) / 256, 256>>>(X, xhi, xlo, M_TOT * D_ / 4);
    mm_bf16x3<<<dim3(24, 64), 256, MM_SMEM>>>(xhi, xlo, 0, 0, nullptr);

    scores_kernel<<<dim3(S_ / 128, S_ / 128, B_ * H_), 256>>>();
    softmax_kernel<<<B_ * H_ * S_, 256>>>();
    ctx_kernel<<<dim3(S_ / 128, B_ * H_), 256>>>();

    split_kernel<<<(M_TOT * D_ / 4 + 255) / 256, 256>>>(ctxp, chi, clo, M_TOT * D_ / 4);
    mm_bf16x3<<<dim3(8, 64), 256, MM_SMEM>>>(chi, clo, 3072, 1, out);
}

// round 11
// speedup vs baseline: 1.8332x; 1.4660x over previous
#include <cuda_runtime.h>
#include <cuda_bf16.h>
#include <cstdint>

#define B_  4
#define S_  2048
#define D_  1024
#define H_  16
#define DH_ 64
#define NEG_INF_ -1000000000.0f
#define M_TOT (B_ * S_)   // 8192
#define BH_ (B_ * H_)     // 64

// ---------------- scratch (__device__ globals) ----------------
__device__ unsigned char g_m8[B_ * S_];
__device__ __nv_bfloat16 g_xhi[(size_t)M_TOT * D_];
__device__ __nv_bfloat16 g_xlo[(size_t)M_TOT * D_];
__device__ __nv_bfloat16 g_chi[(size_t)M_TOT * D_];
__device__ __nv_bfloat16 g_clo[(size_t)M_TOT * D_];
__device__ __nv_bfloat16 g_wt_hi[(size_t)4096 * D_];  // W^T rows: [Wq|Wk|Wv|Wo]
__device__ __nv_bfloat16 g_wt_lo[(size_t)4096 * D_];
__device__ float g_bias[4096];
// attention operands, bf16 hi/lo
__device__ __nv_bfloat16 g_qh[(size_t)BH_ * S_ * DH_];
__device__ __nv_bfloat16 g_ql[(size_t)BH_ * S_ * DH_];
__device__ __nv_bfloat16 g_kh[(size_t)BH_ * S_ * DH_];
__device__ __nv_bfloat16 g_kl[(size_t)BH_ * S_ * DH_];
__device__ __nv_bfloat16 g_vth[(size_t)BH_ * DH_ * S_];  // V^T: [bh][dh][s]
__device__ __nv_bfloat16 g_vtl[(size_t)BH_ * DH_ * S_];

// ---------------- PTX helpers (base-ISA, sm_80+) ----------------
__device__ __forceinline__ uint32_t smem_u32(const void* p) {
    uint32_t a;
    asm("{ .reg .u64 t; cvta.to.shared.u64 t, %1; cvt.u32.u64 %0, t; }" : "=r"(a) : "l"(p));
    return a;
}
__device__ __forceinline__ void cpasync16(uint32_t saddr, const void* gaddr) {
    asm volatile("cp.async.cg.shared.global [%0], [%1], 16;" :: "r"(saddr), "l"(gaddr));
}
__device__ __forceinline__ void cpasync_commit() {
    asm volatile("cp.async.commit_group;" ::: "memory");
}
__device__ __forceinline__ void ldmx4(uint32_t addr, uint32_t* r) {
    asm volatile("ldmatrix.sync.aligned.m8n8.x4.shared.b16 {%0,%1,%2,%3}, [%4];"
                 : "=r"(r[0]), "=r"(r[1]), "=r"(r[2]), "=r"(r[3]) : "r"(addr));
}
__device__ __forceinline__ void mma_bf16(float* d, const uint32_t* a, uint32_t b0, uint32_t b1) {
    asm volatile(
        "mma.sync.aligned.m16n8k16.row.col.f32.bf16.bf16.f32 "
        "{%0,%1,%2,%3}, {%4,%5,%6,%7}, {%8,%9}, {%0,%1,%2,%3};"
        : "+f"(d[0]), "+f"(d[1]), "+f"(d[2]), "+f"(d[3])
        : "r"(a[0]), "r"(a[1]), "r"(a[2]), "r"(a[3]), "r"(b0), "r"(b1));
}
__device__ __forceinline__ uint32_t pack_bf16(float x, float y) {
    __nv_bfloat162 h = __floats2bfloat162_rn(x, y);
    return *(uint32_t*)&h;
}

// ---------------- mask dtype sniff + normalize ----------------
__global__ void mask_prep_kernel(const unsigned char* __restrict__ mraw) {
    __shared__ int flags[3];
    int tid = threadIdx.x;
    if (tid < 3) flags[tid] = 0;
    __syncthreads();
    for (int i = tid; i < B_ * S_; i += blockDim.x) {
        unsigned char b = mraw[i];
        if (b == 0x3f) {
            if ((i & 3) == 3) atomicOr(&flags[0], 1);
            atomicOr(&flags[1], 1);
        } else if (b != 0 && (i & 3) != 0) {
            atomicOr(&flags[2], 1);
        }
    }
    __syncthreads();
    int dtype;
    if (flags[0])      dtype = 2;
    else if (flags[1]) dtype = 3;
    else if (flags[2]) dtype = 0;
    else               dtype = 1;
    for (int i = tid; i < B_ * S_; i += blockDim.x) {
        int v;
        if (dtype == 0)      v = (mraw[i] != 0);
        else if (dtype == 1) v = (((const int*)mraw)[i] != 0);
        else if (dtype == 2) v = (((const float*)mraw)[i] != 0.0f);
        else                 v = (((const unsigned short*)mraw)[i] != 0);
        g_m8[i] = (unsigned char)v;
    }
}

// ---------------- fp32 -> bf16 hi/lo split ----------------
__global__ __launch_bounds__(256) void split_kernel(
    const float* __restrict__ x, __nv_bfloat16* __restrict__ hi,
    __nv_bfloat16* __restrict__ lo, int n4)
{
    int i = blockIdx.x * 256 + threadIdx.x;
    if (i >= n4) return;
    float4 v = ((const float4*)x)[i];
    float vv[4] = {v.x, v.y, v.z, v.w};
    #pragma unroll
    for (int j = 0; j < 4; j++) {
        __nv_bfloat16 h = __float2bfloat16(vv[j]);
        __nv_bfloat16 l = __float2bfloat16(vv[j] - __bfloat162float(h));
        hi[(size_t)i * 4 + j] = h;
        lo[(size_t)i * 4 + j] = l;
    }
}

// ---------------- weight transpose + split ----------------
__global__ void wsplit_kernel(const float* __restrict__ Wq, const float* __restrict__ Wk,
                              const float* __restrict__ Wv, const float* __restrict__ Wo)
{
    __shared__ float t[32][33];
    int mat = blockIdx.z;
    const float* W = (mat == 0) ? Wq : (mat == 1) ? Wk : (mat == 2) ? Wv : Wo;
    int k0 = blockIdx.y * 32, n0 = blockIdx.x * 32;
    int tx = threadIdx.x, ty = threadIdx.y;
    for (int r = ty; r < 32; r += 8)
        t[r][tx] = W[(size_t)(k0 + r) * D_ + n0 + tx];
    __syncthreads();
    for (int r = ty; r < 32; r += 8) {
        float v = t[tx][r];
        __nv_bfloat16 h = __float2bfloat16(v);
        __nv_bfloat16 l = __float2bfloat16(v - __bfloat162float(h));
        size_t o = (size_t)(mat * 1024 + n0 + r) * D_ + k0 + tx;
        g_wt_hi[o] = h;
        g_wt_lo[o] = l;
    }
}

__global__ void bias_kernel(const float* __restrict__ bq, const float* __restrict__ bk,
                            const float* __restrict__ bv, const float* __restrict__ bo)
{
    int i = blockIdx.x * 256 + threadIdx.x;
    if (i >= 4096) return;
    float v;
    if (i < 1024)      v = bq[i];
    else if (i < 2048) v = bk[i - 1024];
    else if (i < 3072) v = bv[i - 2048];
    else               v = bo[i - 3072];
    g_bias[i] = v;
}

// ---------------- mma.sync bf16x3 GEMM ----------------
// CTA 128x128, BK=32, 8 warps (4m x 2n). mode 0: emit Q/K bf16 hi/lo + V^T; mode 1: fp32 out.
#define MMROW 40
#define TILEB (128 * MMROW * 2)
#define STAGEB (4 * TILEB)
#define MM_SMEM (2 * STAGEB)

__global__ __launch_bounds__(256, 1) void mm_bf16x3(
    const __nv_bfloat16* __restrict__ Ahi, const __nv_bfloat16* __restrict__ Alo,
    int n_base_global, int mode, float* __restrict__ out_plain)
{
    extern __shared__ __align__(16) unsigned char dsm[];
    const int tid = threadIdx.x, lane = tid & 31, wid = tid >> 5;
    const int wm = wid >> 1, wn = wid & 1;
    const int m0 = blockIdx.y * 128;
    const int nb = n_base_global + blockIdx.x * 128;
    const uint32_t sbase = smem_u32(dsm);

    const __nv_bfloat16* srcs[4];
    srcs[0] = Ahi + (size_t)m0 * D_;
    srcs[1] = Alo + (size_t)m0 * D_;
    srcs[2] = g_wt_hi + (size_t)nb * D_;
    srcs[3] = g_wt_lo + (size_t)nb * D_;

    float d[2][8][4] = {};
    const int NITER = D_ / 32;

    auto load_stage = [&](int iter, int buf) {
        uint32_t sb = sbase + (uint32_t)buf * STAGEB;
        int k0 = iter * 32;
        #pragma unroll
        for (int t4 = 0; t4 < 4; t4++) {
            const __nv_bfloat16* src = srcs[t4] + k0;
            uint32_t tb = sb + (uint32_t)t4 * TILEB;
            #pragma unroll
            for (int u = 0; u < 2; u++) {
                int c = tid * 2 + u;
                int row = c >> 2, cg = c & 3;
                cpasync16(tb + (uint32_t)(row * 80 + cg * 16),
                          src + (size_t)row * D_ + cg * 8);
            }
        }
        cpasync_commit();
    };

    load_stage(0, 0);

    for (int i = 0; i < NITER; i++) {
        if (i + 1 < NITER) {
            load_stage(i + 1, (i + 1) & 1);
            asm volatile("cp.async.wait_group 1;" ::: "memory");
        } else {
            asm volatile("cp.async.wait_group 0;" ::: "memory");
        }
        __syncthreads();

        uint32_t sb = sbase + (uint32_t)(i & 1) * STAGEB;
        uint32_t aH = sb, aL = sb + TILEB, bH = sb + 2 * TILEB, bL = sb + 3 * TILEB;

        #pragma unroll
        for (int ks = 0; ks < 2; ks++) {
            uint32_t ah[2][4], al[2][4];
            #pragma unroll
            for (int mf = 0; mf < 2; mf++) {
                uint32_t off = (uint32_t)((wm * 32 + mf * 16 + (lane & 15)) * 80 +
                                          (ks * 16 + ((lane >> 4) << 3)) * 2);
                ldmx4(aH + off, ah[mf]);
                ldmx4(aL + off, al[mf]);
            }
            uint32_t bh[4][4], bl[4][4];
            #pragma unroll
            for (int np = 0; np < 4; np++) {
                uint32_t off = (uint32_t)((wn * 64 + np * 16 + ((lane >> 4) << 3) + (lane & 7)) * 80 +
                                          (ks * 16 + ((lane >> 3) & 1) * 8) * 2);
                ldmx4(bH + off, bh[np]);
                ldmx4(bL + off, bl[np]);
            }
            #pragma unroll
            for (int mf = 0; mf < 2; mf++)
                #pragma unroll
                for (int np = 0; np < 4; np++)
                    #pragma unroll
                    for (int half = 0; half < 2; half++) {
                        int nf = np * 2 + half;
                        mma_bf16(d[mf][nf], ah[mf], bh[np][half * 2], bh[np][half * 2 + 1]);
                        mma_bf16(d[mf][nf], al[mf], bh[np][half * 2], bh[np][half * 2 + 1]);
                        mma_bf16(d[mf][nf], ah[mf], bl[np][half * 2], bl[np][half * 2 + 1]);
                    }
        }
        __syncthreads();
    }

    #pragma unroll
    for (int mf = 0; mf < 2; mf++)
        #pragma unroll
        for (int nf = 0; nf < 8; nf++) {
            int row0 = m0 + wm * 32 + mf * 16 + (lane >> 2);
            int colg = nb + wn * 64 + nf * 8 + (lane & 3) * 2;
            float bia0 = g_bias[colg], bia1 = g_bias[colg + 1];
            float xs[2] = {d[mf][nf][0] + bia0, d[mf][nf][2] + bia0};
            float ys[2] = {d[mf][nf][1] + bia1, d[mf][nf][3] + bia1};
            if (mode == 0) {
                int mat = colg >> 10, col = colg & 1023, h = col >> 6, dd = col & 63;
                #pragma unroll
                for (int rr = 0; rr < 2; rr++) {
                    int r = row0 + rr * 8;
                    int bi = r >> 11, s = r & (S_ - 1);
                    float x = xs[rr], y = ys[rr];
                    __nv_bfloat16 hx = __float2bfloat16(x);
                    __nv_bfloat16 hy = __float2bfloat16(y);
                    __nv_bfloat16 lx = __float2bfloat16(x - __bfloat162float(hx));
                    __nv_bfloat16 ly = __float2bfloat16(y - __bfloat162float(hy));
                    if (mat <= 1) {
                        size_t base = (((size_t)(bi * H_ + h)) * S_ + s) * DH_ + dd;
                        __nv_bfloat16* ph = mat == 0 ? g_qh : g_kh;
                        __nv_bfloat16* pl = mat == 0 ? g_ql : g_kl;
                        *(uint32_t*)&ph[base] = pack_bf16(x, y);   // rn-packed hi
                        *(uint32_t*)&pl[base] =
                            ((uint32_t)__bfloat16_as_ushort(ly) << 16) | __bfloat16_as_ushort(lx);
                    } else {  // V transposed
                        size_t base = (((size_t)(bi * H_ + h)) * DH_ + dd) * S_ + s;
                        g_vth[base] = hx; g_vth[base + S_] = hy;
                        g_vtl[base] = lx; g_vtl[base + S_] = ly;
                    }
                }
            } else {
                int n = colg - 3072;
                *(float2*)&out_plain[(size_t)row0 * D_ + n] = make_float2(xs[0], ys[0]);
                *(float2*)&out_plain[(size_t)(row0 + 8) * D_ + n] = make_float2(xs[1], ys[1]);
            }
        }
}

// ---------------- fused flash attention ----------------
// CTA: (qtile of 128 rows, bh). 8 warps x 16 q-rows. KV tiles of 64.
#define RS 72
#define RSB 144
#define FQ_BYTES (128 * RSB)          // 18432 per hi/lo
#define FSTG_SUB (64 * RSB)           // 9216
#define FSTG_BYTES (4 * FSTG_SUB)     // 36864 (Kh,Kl,Vh,Vl)
#define FL_SMEM (2 * FQ_BYTES + 2 * FSTG_BYTES)  // 110592

__global__ __launch_bounds__(256, 1) void flash_kernel() {
    extern __shared__ __align__(16) unsigned char dsm[];
    const int tid = threadIdx.x, lane = tid & 31, wid = tid >> 5;
    const int bh = blockIdx.y, b = bh >> 4, h = bh & 15;
    const int q0 = blockIdx.x * 128;
    const uint32_t sbase = smem_u32(dsm);
    const uint32_t QH = sbase, QL = sbase + FQ_BYTES;

    const __nv_bfloat16* Qh = g_qh + ((size_t)bh * S_ + q0) * DH_;
    const __nv_bfloat16* Ql = g_ql + ((size_t)bh * S_ + q0) * DH_;
    const __nv_bfloat16* Kh = g_kh + (size_t)bh * S_ * DH_;
    const __nv_bfloat16* Kl = g_kl + (size_t)bh * S_ * DH_;
    const __nv_bfloat16* Vh = g_vth + (size_t)bh * DH_ * S_;
    const __nv_bfloat16* Vl = g_vtl + (size_t)bh * DH_ * S_;
    const unsigned char* mk = g_m8 + b * S_;

    // prologue: load Q (once)
    #pragma unroll
    for (int u = 0; u < 4; u++) {
        int c = tid + u * 256;            // 0..1023
        int row = c >> 3, ch = c & 7;
        cpasync16(QH + (uint32_t)(row * RSB + ch * 16), Qh + (size_t)row * DH_ + ch * 8);
        cpasync16(QL + (uint32_t)(row * RSB + ch * 16), Ql + (size_t)row * DH_ + ch * 8);
    }
    cpasync_commit();

    auto load_stage = [&](int t, int buf) {
        uint32_t sb = sbase + 2 * FQ_BYTES + (uint32_t)buf * FSTG_BYTES;
        int kv0 = t * 64;
        #pragma unroll
        for (int u = 0; u < 2; u++) {
            int c = tid * 2 + u;          // 0..511
            int row = c >> 3, ch = c & 7;
            uint32_t so = (uint32_t)(row * RSB + ch * 16);
            cpasync16(sb + so,                Kh + (size_t)(kv0 + row) * DH_ + ch * 8);
            cpasync16(sb + FSTG_SUB + so,     Kl + (size_t)(kv0 + row) * DH_ + ch * 8);
            cpasync16(sb + 2 * FSTG_SUB + so, Vh + (size_t)row * S_ + kv0 + ch * 8);
            cpasync16(sb + 3 * FSTG_SUB + so, Vl + (size_t)row * S_ + kv0 + ch * 8);
        }
        cpasync_commit();
    };

    load_stage(0, 0);

    float S[8][4], O[8][4] = {};
    float m0r = -3.4e38f, m1r = -3.4e38f, l0 = 0.0f, l1 = 0.0f;
    const int NT = S_ / 64;  // 32

    for (int t = 0; t < NT; t++) {
        if (t + 1 < NT) {
            load_stage(t + 1, (t + 1) & 1);
            asm volatile("cp.async.wait_group 1;" ::: "memory");
        } else {
            asm volatile("cp.async.wait_group 0;" ::: "memory");
        }
        __syncthreads();

        uint32_t sb = sbase + 2 * FQ_BYTES + (uint32_t)(t & 1) * FSTG_BYTES;
        uint32_t KHs = sb, KLs = sb + FSTG_SUB, VHs = sb + 2 * FSTG_SUB, VLs = sb + 3 * FSTG_SUB;
        int kv0 = t * 64;

        #pragma unroll
        for (int nf = 0; nf < 8; nf++)
            #pragma unroll
            for (int j = 0; j < 4; j++) S[nf][j] = 0.0f;

        // ---- S = Q @ K^T (bf16x3) ----
        #pragma unroll
        for (int ks = 0; ks < 4; ks++) {
            uint32_t qa_h[4], qa_l[4];
            uint32_t aoff = (uint32_t)((wid * 16 + (lane & 15)) * RSB +
                                       (ks * 16 + ((lane >> 4) << 3)) * 2);
            ldmx4(QH + aoff, qa_h);
            ldmx4(QL + aoff, qa_l);
            uint32_t kb_h[4][4], kb_l[4][4];
            #pragma unroll
            for (int np = 0; np < 4; np++) {
                uint32_t boff = (uint32_t)((np * 16 + ((lane >> 4) << 3) + (lane & 7)) * RSB +
                                           (ks * 16 + ((lane >> 3) & 1) * 8) * 2);
                ldmx4(KHs + boff, kb_h[np]);
                ldmx4(KLs + boff, kb_l[np]);
            }
            #pragma unroll
            for (int np = 0; np < 4; np++)
                #pragma unroll
                for (int hf = 0; hf < 2; hf++)
                    mma_bf16(S[np * 2 + hf], qa_h, kb_h[np][hf * 2], kb_h[np][hf * 2 + 1]);
            #pragma unroll
            for (int np = 0; np < 4; np++)
                #pragma unroll
                for (int hf = 0; hf < 2; hf++)
                    mma_bf16(S[np * 2 + hf], qa_l, kb_h[np][hf * 2], kb_h[np][hf * 2 + 1]);
            #pragma unroll
            for (int np = 0; np < 4; np++)
                #pragma unroll
                for (int hf = 0; hf < 2; hf++)
                    mma_bf16(S[np * 2 + hf], qa_h, kb_l[np][hf * 2], kb_l[np][hf * 2 + 1]);
        }

        // ---- key mask + online softmax ----
        #pragma unroll
        for (int nf = 0; nf < 8; nf++) {
            int c = kv0 + nf * 8 + (lane & 3) * 2;
            unsigned short mp = *(const unsigned short*)&mk[c];
            if (!(mp & 0x00ff)) { S[nf][0] = NEG_INF_; S[nf][2] = NEG_INF_; }
            if (!(mp & 0xff00)) { S[nf][1] = NEG_INF_; S[nf][3] = NEG_INF_; }
        }
        float mn0 = -3.4e38f, mn1 = -3.4e38f;
        #pragma unroll
        for (int nf = 0; nf < 8; nf++) {
            mn0 = fmaxf(mn0, fmaxf(S[nf][0], S[nf][1]));
            mn1 = fmaxf(mn1, fmaxf(S[nf][2], S[nf][3]));
        }
        mn0 = fmaxf(mn0, __shfl_xor_sync(0xffffffffu, mn0, 1));
        mn0 = fmaxf(mn0, __shfl_xor_sync(0xffffffffu, mn0, 2));
        mn1 = fmaxf(mn1, __shfl_xor_sync(0xffffffffu, mn1, 1));
        mn1 = fmaxf(mn1, __shfl_xor_sync(0xffffffffu, mn1, 2));
        float m0n = fmaxf(m0r, mn0), m1n = fmaxf(m1r, mn1);
        float sc0 = __expf(m0r - m0n), sc1 = __expf(m1r - m1n);
        m0r = m0n; m1r = m1n;
        float ps0 = 0.0f, ps1 = 0.0f;
        #pragma unroll
        for (int nf = 0; nf < 8; nf++) {
            S[nf][0] = __expf(S[nf][0] - m0n);
            S[nf][1] = __expf(S[nf][1] - m0n);
            S[nf][2] = __expf(S[nf][2] - m1n);
            S[nf][3] = __expf(S[nf][3] - m1n);
            ps0 += S[nf][0] + S[nf][1];
            ps1 += S[nf][2] + S[nf][3];
        }
        l0 = l0 * sc0 + ps0;
        l1 = l1 * sc1 + ps1;
        #pragma unroll
        for (int nf = 0; nf < 8; nf++) {
            O[nf][0] *= sc0; O[nf][1] *= sc0;
            O[nf][2] *= sc1; O[nf][3] *= sc1;
        }

        // ---- O += P @ V (bf16x3; P A-frags from S regs) ----
        #pragma unroll
        for (int ks = 0; ks < 4; ks++) {
            uint32_t ph[4], pl[4];
            {
                float s00 = S[2 * ks][0],     s01 = S[2 * ks][1];
                float s02 = S[2 * ks][2],     s03 = S[2 * ks][3];
                float s10 = S[2 * ks + 1][0], s11 = S[2 * ks + 1][1];
                float s12 = S[2 * ks + 1][2], s13 = S[2 * ks + 1][3];
                ph[0] = pack_bf16(s00, s01);
                ph[1] = pack_bf16(s02, s03);
                ph[2] = pack_bf16(s10, s11);
                ph[3] = pack_bf16(s12, s13);
                __nv_bfloat162 h0 = *(__nv_bfloat162*)&ph[0];
                __nv_bfloat162 h1 = *(__nv_bfloat162*)&ph[1];
                __nv_bfloat162 h2 = *(__nv_bfloat162*)&ph[2];
                __nv_bfloat162 h3 = *(__nv_bfloat162*)&ph[3];
                pl[0] = pack_bf16(s00 - __bfloat162float(h0.x), s01 - __bfloat162float(h0.y));
                pl[1] = pack_bf16(s02 - __bfloat162float(h1.x), s03 - __bfloat162float(h1.y));
                pl[2] = pack_bf16(s10 - __bfloat162float(h2.x), s11 - __bfloat162float(h2.y));
                pl[3] = pack_bf16(s12 - __bfloat162float(h3.x), s13 - __bfloat162float(h3.y));
            }
            uint32_t vb_h[4][4], vb_l[4][4];
            #pragma unroll
            for (int np = 0; np < 4; np++) {
                uint32_t boff = (uint32_t)((np * 16 + ((lane >> 4) << 3) + (lane & 7)) * RSB +
                                           (ks * 16 + ((lane >> 3) & 1) * 8) * 2);
                ldmx4(VHs + boff, vb_h[np]);
                ldmx4(VLs + boff, vb_l[np]);
            }
            #pragma unroll
            for (int np = 0; np < 4; np++)
                #pragma unroll
                for (int hf = 0; hf < 2; hf++)
                    mma_bf16(O[np * 2 + hf], ph, vb_h[np][hf * 2], vb_h[np][hf * 2 + 1]);
            #pragma unroll
            for (int np = 0; np < 4; np++)
                #pragma unroll
                for (int hf = 0; hf < 2; hf++)
                    mma_bf16(O[np * 2 + hf], pl, vb_h[np][hf * 2], vb_h[np][hf * 2 + 1]);
            #pragma unroll
            for (int np = 0; np < 4; np++)
                #pragma unroll
                for (int hf = 0; hf < 2; hf++)
                    mma_bf16(O[np * 2 + hf], ph, vb_l[np][hf * 2], vb_l[np][hf * 2 + 1]);
        }
        __syncthreads();
    }

    // ---- epilogue: normalize, query-mask, bf16 hi/lo, store to g_chi/g_clo ----
    l0 += __shfl_xor_sync(0xffffffffu, l0, 1);
    l0 += __shfl_xor_sync(0xffffffffu, l0, 2);
    l1 += __shfl_xor_sync(0xffffffffu, l1, 1);
    l1 += __shfl_xor_sync(0xffffffffu, l1, 2);
    int r0 = q0 + wid * 16 + (lane >> 2);
    int r1 = r0 + 8;
    float f0 = (mk[r0] ? 1.0f : 0.0f) / l0;
    float f1 = (mk[r1] ? 1.0f : 0.0f) / l1;
    size_t gm0 = (size_t)(b * S_ + r0) * D_;
    size_t gm1 = (size_t)(b * S_ + r1) * D_;
    #pragma unroll
    for (int nf = 0; nf < 8; nf++) {
        int col = h * DH_ + nf * 8 + (lane & 3) * 2;
        float x0 = O[nf][0] * f0, y0 = O[nf][1] * f0;
        float x1 = O[nf][2] * f1, y1 = O[nf][3] * f1;
        uint32_t h0 = pack_bf16(x0, y0), h1 = pack_bf16(x1, y1);
        __nv_bfloat162 hh0 = *(__nv_bfloat162*)&h0;
        __nv_bfloat162 hh1 = *(__nv_bfloat162*)&h1;
        uint32_t lo0 = pack_bf16(x0 - __bfloat162float(hh0.x), y0 - __bfloat162float(hh0.y));
        uint32_t lo1 = pack_bf16(x1 - __bfloat162float(hh1.x), y1 - __bfloat162float(hh1.y));
        *(uint32_t*)&g_chi[gm0 + col] = h0;
        *(uint32_t*)&g_clo[gm0 + col] = lo0;
        *(uint32_t*)&g_chi[gm1 + col] = h1;
        *(uint32_t*)&g_clo[gm1 + col] = lo1;
    }
}

// ---------------- launch ----------------
extern "C" void kernel_launch(void* const* d_in, const int* in_sizes, int n_in,
                              void* d_out, int out_size) {
    (void)in_sizes; (void)n_in; (void)out_size;
    const float* X  = (const float*)d_in[0];
    const unsigned char* mask = (const unsigned char*)d_in[1];
    const float* Wq = (const float*)d_in[2];
    const float* bq = (const float*)d_in[3];
    const float* Wk = (const float*)d_in[4];
    const float* bk = (const float*)d_in[5];
    const float* Wv = (const float*)d_in[6];
    const float* bv = (const float*)d_in[7];
    const float* Wo = (const float*)d_in[8];
    const float* bo = (const float*)d_in[9];
    float* out = (float*)d_out;

    cudaFuncSetAttribute(mm_bf16x3, cudaFuncAttributeMaxDynamicSharedMemorySize, MM_SMEM);
    cudaFuncSetAttribute(flash_kernel, cudaFuncAttributeMaxDynamicSharedMemorySize, FL_SMEM);

    __nv_bfloat16 *xhi, *xlo, *chi, *clo;
    cudaGetSymbolAddress((void**)&xhi, g_xhi);
    cudaGetSymbolAddress((void**)&xlo, g_xlo);
    cudaGetSymbolAddress((void**)&chi, g_chi);
    cudaGetSymbolAddress((void**)&clo, g_clo);

    mask_prep_kernel<<<1, 256>>>(mask);
    wsplit_kernel<<<dim3(32, 32, 4), dim3(32, 8)>>>(Wq, Wk, Wv, Wo);
    bias_kernel<<<16, 256>>>(bq, bk, bv, bo);
    split_kernel<<<(M_TOT * D_ / 4 + 255) / 256, 256>>>(X, xhi, xlo, M_TOT * D_ / 4);
    mm_bf16x3<<<dim3(24, 64), 256, MM_SMEM>>>(xhi, xlo, 0, 0, nullptr);

    flash_kernel<<<dim3(S_ / 128, BH_), 256, FL_SMEM>>>();

    mm_bf16x3<<<dim3(8, 64), 256, MM_SMEM>>>(chi, clo, 3072, 1, out);
}

// round 13
// speedup vs baseline: 3.0191x; 1.6468x over previous
#include <cuda_runtime.h>
#include <cuda_bf16.h>
#include <cstdint>

#define B_  4
#define S_  2048
#define D_  1024
#define H_  16
#define DH_ 64
#define NEG_INF_ -1000000000.0f
#define M_TOT (B_ * S_)   // 8192
#define BH_ (B_ * H_)     // 64

// ---------------- scratch (__device__ globals) ----------------
__device__ unsigned char g_m8[B_ * S_];
__device__ __nv_bfloat16 g_xhi[(size_t)M_TOT * D_];
__device__ __nv_bfloat16 g_xlo[(size_t)M_TOT * D_];
__device__ __nv_bfloat16 g_chi[(size_t)M_TOT * D_];
__device__ __nv_bfloat16 g_clo[(size_t)M_TOT * D_];
__device__ __nv_bfloat16 g_wt_hi[(size_t)4096 * D_];  // W^T rows: [Wq|Wk|Wv|Wo]
__device__ __nv_bfloat16 g_wt_lo[(size_t)4096 * D_];
__device__ float g_bias[4096];
// attention operands, bf16 hi/lo
__device__ __nv_bfloat16 g_qh[(size_t)BH_ * S_ * DH_];
__device__ __nv_bfloat16 g_ql[(size_t)BH_ * S_ * DH_];
__device__ __nv_bfloat16 g_kh[(size_t)BH_ * S_ * DH_];
__device__ __nv_bfloat16 g_kl[(size_t)BH_ * S_ * DH_];
__device__ __nv_bfloat16 g_vth[(size_t)BH_ * DH_ * S_];  // V^T: [bh][dh][s]
__device__ __nv_bfloat16 g_vtl[(size_t)BH_ * DH_ * S_];

// ---------------- PTX helpers (base-ISA, sm_80+) ----------------
__device__ __forceinline__ uint32_t smem_u32(const void* p) {
    uint32_t a;
    asm("{ .reg .u64 t; cvta.to.shared.u64 t, %1; cvt.u32.u64 %0, t; }" : "=r"(a) : "l"(p));
    return a;
}
__device__ __forceinline__ void cpasync16(uint32_t saddr, const void* gaddr) {
    asm volatile("cp.async.cg.shared.global [%0], [%1], 16;" :: "r"(saddr), "l"(gaddr));
}
__device__ __forceinline__ void cpasync_commit() {
    asm volatile("cp.async.commit_group;" ::: "memory");
}
__device__ __forceinline__ void ldmx4(uint32_t addr, uint32_t* r) {
    asm volatile("ldmatrix.sync.aligned.m8n8.x4.shared.b16 {%0,%1,%2,%3}, [%4];"
                 : "=r"(r[0]), "=r"(r[1]), "=r"(r[2]), "=r"(r[3]) : "r"(addr));
}
__device__ __forceinline__ void mma_bf16(float* d, const uint32_t* a, uint32_t b0, uint32_t b1) {
    asm volatile(
        "mma.sync.aligned.m16n8k16.row.col.f32.bf16.bf16.f32 "
        "{%0,%1,%2,%3}, {%4,%5,%6,%7}, {%8,%9}, {%0,%1,%2,%3};"
        : "+f"(d[0]), "+f"(d[1]), "+f"(d[2]), "+f"(d[3])
        : "r"(a[0]), "r"(a[1]), "r"(a[2]), "r"(a[3]), "r"(b0), "r"(b1));
}
__device__ __forceinline__ uint32_t pack_bf16(float x, float y) {
    __nv_bfloat162 h = __floats2bfloat162_rn(x, y);
    return *(uint32_t*)&h;
}

// ---------------- mask dtype sniff + normalize ----------------
__global__ void mask_prep_kernel(const unsigned char* __restrict__ mraw) {
    __shared__ int flags[3];
    int tid = threadIdx.x;
    if (tid < 3) flags[tid] = 0;
    __syncthreads();
    for (int i = tid; i < B_ * S_; i += blockDim.x) {
        unsigned char b = mraw[i];
        if (b == 0x3f) {
            if ((i & 3) == 3) atomicOr(&flags[0], 1);
            atomicOr(&flags[1], 1);
        } else if (b != 0 && (i & 3) != 0) {
            atomicOr(&flags[2], 1);
        }
    }
    __syncthreads();
    int dtype;
    if (flags[0])      dtype = 2;
    else if (flags[1]) dtype = 3;
    else if (flags[2]) dtype = 0;
    else               dtype = 1;
    for (int i = tid; i < B_ * S_; i += blockDim.x) {
        int v;
        if (dtype == 0)      v = (mraw[i] != 0);
        else if (dtype == 1) v = (((const int*)mraw)[i] != 0);
        else if (dtype == 2) v = (((const float*)mraw)[i] != 0.0f);
        else                 v = (((const unsigned short*)mraw)[i] != 0);
        g_m8[i] = (unsigned char)v;
    }
}

// ---------------- fp32 -> bf16 hi/lo split (4x float4 per thread for MLP) ----------------
__global__ __launch_bounds__(256) void split_kernel(
    const float* __restrict__ x, __nv_bfloat16* __restrict__ hi,
    __nv_bfloat16* __restrict__ lo, int n4)
{
    int base = blockIdx.x * 256 + threadIdx.x;
    int stride = gridDim.x * 256;
    float4 v[4];
    int idx[4];
    #pragma unroll
    for (int u = 0; u < 4; u++) {
        idx[u] = base + u * stride;
        if (idx[u] < n4) v[u] = ((const float4*)x)[idx[u]];
    }
    #pragma unroll
    for (int u = 0; u < 4; u++) {
        if (idx[u] >= n4) continue;
        float vv[4] = {v[u].x, v[u].y, v[u].z, v[u].w};
        #pragma unroll
        for (int j = 0; j < 4; j++) {
            __nv_bfloat16 h = __float2bfloat16(vv[j]);
            __nv_bfloat16 l = __float2bfloat16(vv[j] - __bfloat162float(h));
            hi[(size_t)idx[u] * 4 + j] = h;
            lo[(size_t)idx[u] * 4 + j] = l;
        }
    }
}

// ---------------- weight transpose + split ----------------
__global__ void wsplit_kernel(const float* __restrict__ Wq, const float* __restrict__ Wk,
                              const float* __restrict__ Wv, const float* __restrict__ Wo)
{
    __shared__ float t[32][33];
    int mat = blockIdx.z;
    const float* W = (mat == 0) ? Wq : (mat == 1) ? Wk : (mat == 2) ? Wv : Wo;
    int k0 = blockIdx.y * 32, n0 = blockIdx.x * 32;
    int tx = threadIdx.x, ty = threadIdx.y;
    for (int r = ty; r < 32; r += 8)
        t[r][tx] = W[(size_t)(k0 + r) * D_ + n0 + tx];
    __syncthreads();
    for (int r = ty; r < 32; r += 8) {
        float v = t[tx][r];
        __nv_bfloat16 h = __float2bfloat16(v);
        __nv_bfloat16 l = __float2bfloat16(v - __bfloat162float(h));
        size_t o = (size_t)(mat * 1024 + n0 + r) * D_ + k0 + tx;
        g_wt_hi[o] = h;
        g_wt_lo[o] = l;
    }
}

__global__ void bias_kernel(const float* __restrict__ bq, const float* __restrict__ bk,
                            const float* __restrict__ bv, const float* __restrict__ bo)
{
    int i = blockIdx.x * 256 + threadIdx.x;
    if (i >= 4096) return;
    float v;
    if (i < 1024)      v = bq[i];
    else if (i < 2048) v = bk[i - 1024];
    else if (i < 3072) v = bv[i - 2048];
    else               v = bo[i - 3072];
    g_bias[i] = v;
}

// ---------------- mma.sync bf16x3 GEMM ----------------
// CTA 128x128, BK=32, 8 warps (4m x 2n). 2 CTAs/SM (low live-register inner loop).
// mode 0: emit Q/K bf16 hi/lo + V^T; mode 1: fp32 out.
#define MMROW 40
#define TILEB (128 * MMROW * 2)
#define STAGEB (4 * TILEB)
#define MM_SMEM (2 * STAGEB)

__global__ __launch_bounds__(256, 2) void mm_bf16x3(
    const __nv_bfloat16* __restrict__ Ahi, const __nv_bfloat16* __restrict__ Alo,
    int n_base_global, int mode, float* __restrict__ out_plain)
{
    extern __shared__ __align__(16) unsigned char dsm[];
    const int tid = threadIdx.x, lane = tid & 31, wid = tid >> 5;
    const int wm = wid >> 1, wn = wid & 1;
    const int m0 = blockIdx.y * 128;
    const int nb = n_base_global + blockIdx.x * 128;
    const uint32_t sbase = smem_u32(dsm);

    const __nv_bfloat16* srcs[4];
    srcs[0] = Ahi + (size_t)m0 * D_;
    srcs[1] = Alo + (size_t)m0 * D_;
    srcs[2] = g_wt_hi + (size_t)nb * D_;
    srcs[3] = g_wt_lo + (size_t)nb * D_;

    float d[2][8][4] = {};
    const int NITER = D_ / 32;

    auto load_stage = [&](int iter, int buf) {
        uint32_t sb = sbase + (uint32_t)buf * STAGEB;
        int k0 = iter * 32;
        #pragma unroll
        for (int t4 = 0; t4 < 4; t4++) {
            const __nv_bfloat16* src = srcs[t4] + k0;
            uint32_t tb = sb + (uint32_t)t4 * TILEB;
            #pragma unroll
            for (int u = 0; u < 2; u++) {
                int c = tid * 2 + u;
                int row = c >> 2, cg = c & 3;
                cpasync16(tb + (uint32_t)(row * 80 + cg * 16),
                          src + (size_t)row * D_ + cg * 8);
            }
        }
        cpasync_commit();
    };

    load_stage(0, 0);

    for (int i = 0; i < NITER; i++) {
        if (i + 1 < NITER) {
            load_stage(i + 1, (i + 1) & 1);
            asm volatile("cp.async.wait_group 1;" ::: "memory");
        } else {
            asm volatile("cp.async.wait_group 0;" ::: "memory");
        }
        __syncthreads();

        uint32_t sb = sbase + (uint32_t)(i & 1) * STAGEB;
        uint32_t aH = sb, aL = sb + TILEB, bH = sb + 2 * TILEB, bL = sb + 3 * TILEB;

        #pragma unroll
        for (int ks = 0; ks < 2; ks++) {
            uint32_t ah[2][4], al[2][4];
            #pragma unroll
            for (int mf = 0; mf < 2; mf++) {
                uint32_t off = (uint32_t)((wm * 32 + mf * 16 + (lane & 15)) * 80 +
                                          (ks * 16 + ((lane >> 4) << 3)) * 2);
                ldmx4(aH + off, ah[mf]);
                ldmx4(aL + off, al[mf]);
            }
            // process B fragments one np at a time: live B regs = 8 (keeps 2 CTAs/SM spill-free)
            #pragma unroll
            for (int np = 0; np < 4; np++) {
                uint32_t bh[4], bl[4];
                uint32_t off = (uint32_t)((wn * 64 + np * 16 + ((lane >> 4) << 3) + (lane & 7)) * 80 +
                                          (ks * 16 + ((lane >> 3) & 1) * 8) * 2);
                ldmx4(bH + off, bh);
                ldmx4(bL + off, bl);
                #pragma unroll
                for (int mf = 0; mf < 2; mf++)
                    #pragma unroll
                    for (int half = 0; half < 2; half++) {
                        int nf = np * 2 + half;
                        mma_bf16(d[mf][nf], ah[mf], bh[half * 2], bh[half * 2 + 1]);
                        mma_bf16(d[mf][nf], al[mf], bh[half * 2], bh[half * 2 + 1]);
                        mma_bf16(d[mf][nf], ah[mf], bl[half * 2], bl[half * 2 + 1]);
                    }
            }
        }
        __syncthreads();
    }

    #pragma unroll
    for (int mf = 0; mf < 2; mf++)
        #pragma unroll
        for (int nf = 0; nf < 8; nf++) {
            int row0 = m0 + wm * 32 + mf * 16 + (lane >> 2);
            int colg = nb + wn * 64 + nf * 8 + (lane & 3) * 2;
            float bia0 = g_bias[colg], bia1 = g_bias[colg + 1];
            float xs[2] = {d[mf][nf][0] + bia0, d[mf][nf][2] + bia0};
            float ys[2] = {d[mf][nf][1] + bia1, d[mf][nf][3] + bia1};
            if (mode == 0) {
                int mat = colg >> 10, col = colg & 1023, h = col >> 6, dd = col & 63;
                #pragma unroll
                for (int rr = 0; rr < 2; rr++) {
                    int r = row0 + rr * 8;
                    int bi = r >> 11, s = r & (S_ - 1);
                    float x = xs[rr], y = ys[rr];
                    __nv_bfloat16 hx = __float2bfloat16(x);
                    __nv_bfloat16 hy = __float2bfloat16(y);
                    __nv_bfloat16 lx = __float2bfloat16(x - __bfloat162float(hx));
                    __nv_bfloat16 ly = __float2bfloat16(y - __bfloat162float(hy));
                    if (mat <= 1) {
                        size_t base = (((size_t)(bi * H_ + h)) * S_ + s) * DH_ + dd;
                        __nv_bfloat16* ph = mat == 0 ? g_qh : g_kh;
                        __nv_bfloat16* pl = mat == 0 ? g_ql : g_kl;
                        *(uint32_t*)&ph[base] = pack_bf16(x, y);
                        *(uint32_t*)&pl[base] =
                            ((uint32_t)__bfloat16_as_ushort(ly) << 16) | __bfloat16_as_ushort(lx);
                    } else {  // V transposed
                        size_t base = (((size_t)(bi * H_ + h)) * DH_ + dd) * S_ + s;
                        g_vth[base] = hx; g_vth[base + S_] = hy;
                        g_vtl[base] = lx; g_vtl[base + S_] = ly;
                    }
                }
            } else {
                int n = colg - 3072;
                *(float2*)&out_plain[(size_t)row0 * D_ + n] = make_float2(xs[0], ys[0]);
                *(float2*)&out_plain[(size_t)(row0 + 8) * D_ + n] = make_float2(xs[1], ys[1]);
            }
        }
}

// ---------------- fused flash attention (unchanged from R11 — verified) ----------------
#define RS 72
#define RSB 144
#define FQ_BYTES (128 * RSB)
#define FSTG_SUB (64 * RSB)
#define FSTG_BYTES (4 * FSTG_SUB)
#define FL_SMEM (2 * FQ_BYTES + 2 * FSTG_BYTES)  // 110592

__global__ __launch_bounds__(256, 1) void flash_kernel() {
    extern __shared__ __align__(16) unsigned char dsm[];
    const int tid = threadIdx.x, lane = tid & 31, wid = tid >> 5;
    const int bh = blockIdx.y, b = bh >> 4, h = bh & 15;
    const int q0 = blockIdx.x * 128;
    const uint32_t sbase = smem_u32(dsm);
    const uint32_t QH = sbase, QL = sbase + FQ_BYTES;

    const __nv_bfloat16* Qh = g_qh + ((size_t)bh * S_ + q0) * DH_;
    const __nv_bfloat16* Ql = g_ql + ((size_t)bh * S_ + q0) * DH_;
    const __nv_bfloat16* Kh = g_kh + (size_t)bh * S_ * DH_;
    const __nv_bfloat16* Kl = g_kl + (size_t)bh * S_ * DH_;
    const __nv_bfloat16* Vh = g_vth + (size_t)bh * DH_ * S_;
    const __nv_bfloat16* Vl = g_vtl + (size_t)bh * DH_ * S_;
    const unsigned char* mk = g_m8 + b * S_;

    #pragma unroll
    for (int u = 0; u < 4; u++) {
        int c = tid + u * 256;
        int row = c >> 3, ch = c & 7;
        cpasync16(QH + (uint32_t)(row * RSB + ch * 16), Qh + (size_t)row * DH_ + ch * 8);
        cpasync16(QL + (uint32_t)(row * RSB + ch * 16), Ql + (size_t)row * DH_ + ch * 8);
    }
    cpasync_commit();

    auto load_stage = [&](int t, int buf) {
        uint32_t sb = sbase + 2 * FQ_BYTES + (uint32_t)buf * FSTG_BYTES;
        int kv0 = t * 64;
        #pragma unroll
        for (int u = 0; u < 2; u++) {
            int c = tid * 2 + u;
            int row = c >> 3, ch = c & 7;
            uint32_t so = (uint32_t)(row * RSB + ch * 16);
            cpasync16(sb + so,                Kh + (size_t)(kv0 + row) * DH_ + ch * 8);
            cpasync16(sb + FSTG_SUB + so,     Kl + (size_t)(kv0 + row) * DH_ + ch * 8);
            cpasync16(sb + 2 * FSTG_SUB + so, Vh + (size_t)row * S_ + kv0 + ch * 8);
            cpasync16(sb + 3 * FSTG_SUB + so, Vl + (size_t)row * S_ + kv0 + ch * 8);
        }
        cpasync_commit();
    };

    load_stage(0, 0);

    float S[8][4], O[8][4] = {};
    float m0r = -3.4e38f, m1r = -3.4e38f, l0 = 0.0f, l1 = 0.0f;
    const int NT = S_ / 64;

    for (int t = 0; t < NT; t++) {
        if (t + 1 < NT) {
            load_stage(t + 1, (t + 1) & 1);
            asm volatile("cp.async.wait_group 1;" ::: "memory");
        } else {
            asm volatile("cp.async.wait_group 0;" ::: "memory");
        }
        __syncthreads();

        uint32_t sb = sbase + 2 * FQ_BYTES + (uint32_t)(t & 1) * FSTG_BYTES;
        uint32_t KHs = sb, KLs = sb + FSTG_SUB, VHs = sb + 2 * FSTG_SUB, VLs = sb + 3 * FSTG_SUB;
        int kv0 = t * 64;

        #pragma unroll
        for (int nf = 0; nf < 8; nf++)
            #pragma unroll
            for (int j = 0; j < 4; j++) S[nf][j] = 0.0f;

        #pragma unroll
        for (int ks = 0; ks < 4; ks++) {
            uint32_t qa_h[4], qa_l[4];
            uint32_t aoff = (uint32_t)((wid * 16 + (lane & 15)) * RSB +
                                       (ks * 16 + ((lane >> 4) << 3)) * 2);
            ldmx4(QH + aoff, qa_h);
            ldmx4(QL + aoff, qa_l);
            uint32_t kb_h[4][4], kb_l[4][4];
            #pragma unroll
            for (int np = 0; np < 4; np++) {
                uint32_t boff = (uint32_t)((np * 16 + ((lane >> 4) << 3) + (lane & 7)) * RSB +
                                           (ks * 16 + ((lane >> 3) & 1) * 8) * 2);
                ldmx4(KHs + boff, kb_h[np]);
                ldmx4(KLs + boff, kb_l[np]);
            }
            #pragma unroll
            for (int np = 0; np < 4; np++)
                #pragma unroll
                for (int hf = 0; hf < 2; hf++)
                    mma_bf16(S[np * 2 + hf], qa_h, kb_h[np][hf * 2], kb_h[np][hf * 2 + 1]);
            #pragma unroll
            for (int np = 0; np < 4; np++)
                #pragma unroll
                for (int hf = 0; hf < 2; hf++)
                    mma_bf16(S[np * 2 + hf], qa_l, kb_h[np][hf * 2], kb_h[np][hf * 2 + 1]);
            #pragma unroll
            for (int np = 0; np < 4; np++)
                #pragma unroll
                for (int hf = 0; hf < 2; hf++)
                    mma_bf16(S[np * 2 + hf], qa_h, kb_l[np][hf * 2], kb_l[np][hf * 2 + 1]);
        }

        #pragma unroll
        for (int nf = 0; nf < 8; nf++) {
            int c = kv0 + nf * 8 + (lane & 3) * 2;
            unsigned short mp = *(const unsigned short*)&mk[c];
            if (!(mp & 0x00ff)) { S[nf][0] = NEG_INF_; S[nf][2] = NEG_INF_; }
            if (!(mp & 0xff00)) { S[nf][1] = NEG_INF_; S[nf][3] = NEG_INF_; }
        }
        float mn0 = -3.4e38f, mn1 = -3.4e38f;
        #pragma unroll
        for (int nf = 0; nf < 8; nf++) {
            mn0 = fmaxf(mn0, fmaxf(S[nf][0], S[nf][1]));
            mn1 = fmaxf(mn1, fmaxf(S[nf][2], S[nf][3]));
        }
        mn0 = fmaxf(mn0, __shfl_xor_sync(0xffffffffu, mn0, 1));
        mn0 = fmaxf(mn0, __shfl_xor_sync(0xffffffffu, mn0, 2));
        mn1 = fmaxf(mn1, __shfl_xor_sync(0xffffffffu, mn1, 1));
        mn1 = fmaxf(mn1, __shfl_xor_sync(0xffffffffu, mn1, 2));
        float m0n = fmaxf(m0r, mn0), m1n = fmaxf(m1r, mn1);
        float sc0 = __expf(m0r - m0n), sc1 = __expf(m1r - m1n);
        m0r = m0n; m1r = m1n;
        float ps0 = 0.0f, ps1 = 0.0f;
        #pragma unroll
        for (int nf = 0; nf < 8; nf++) {
            S[nf][0] = __expf(S[nf][0] - m0n);
            S[nf][1] = __expf(S[nf][1] - m0n);
            S[nf][2] = __expf(S[nf][2] - m1n);
            S[nf][3] = __expf(S[nf][3] - m1n);
            ps0 += S[nf][0] + S[nf][1];
            ps1 += S[nf][2] + S[nf][3];
        }
        l0 = l0 * sc0 + ps0;
        l1 = l1 * sc1 + ps1;
        #pragma unroll
        for (int nf = 0; nf < 8; nf++) {
            O[nf][0] *= sc0; O[nf][1] *= sc0;
            O[nf][2] *= sc1; O[nf][3] *= sc1;
        }

        #pragma unroll
        for (int ks = 0; ks < 4; ks++) {
            uint32_t ph[4], pl[4];
            {
                float s00 = S[2 * ks][0],     s01 = S[2 * ks][1];
                float s02 = S[2 * ks][2],     s03 = S[2 * ks][3];
                float s10 = S[2 * ks + 1][0], s11 = S[2 * ks + 1][1];
                float s12 = S[2 * ks + 1][2], s13 = S[2 * ks + 1][3];
                ph[0] = pack_bf16(s00, s01);
                ph[1] = pack_bf16(s02, s03);
                ph[2] = pack_bf16(s10, s11);
                ph[3] = pack_bf16(s12, s13);
                __nv_bfloat162 h0 = *(__nv_bfloat162*)&ph[0];
                __nv_bfloat162 h1 = *(__nv_bfloat162*)&ph[1];
                __nv_bfloat162 h2 = *(__nv_bfloat162*)&ph[2];
                __nv_bfloat162 h3 = *(__nv_bfloat162*)&ph[3];
                pl[0] = pack_bf16(s00 - __bfloat162float(h0.x), s01 - __bfloat162float(h0.y));
                pl[1] = pack_bf16(s02 - __bfloat162float(h1.x), s03 - __bfloat162float(h1.y));
                pl[2] = pack_bf16(s10 - __bfloat162float(h2.x), s11 - __bfloat162float(h2.y));
                pl[3] = pack_bf16(s12 - __bfloat162float(h3.x), s13 - __bfloat162float(h3.y));
            }
            uint32_t vb_h[4][4], vb_l[4][4];
            #pragma unroll
            for (int np = 0; np < 4; np++) {
                uint32_t boff = (uint32_t)((np * 16 + ((lane >> 4) << 3) + (lane & 7)) * RSB +
                                           (ks * 16 + ((lane >> 3) & 1) * 8) * 2);
                ldmx4(VHs + boff, vb_h[np]);
                ldmx4(VLs + boff, vb_l[np]);
            }
            #pragma unroll
            for (int np = 0; np < 4; np++)
                #pragma unroll
                for (int hf = 0; hf < 2; hf++)
                    mma_bf16(O[np * 2 + hf], ph, vb_h[np][hf * 2], vb_h[np][hf * 2 + 1]);
            #pragma unroll
            for (int np = 0; np < 4; np++)
                #pragma unroll
                for (int hf = 0; hf < 2; hf++)
                    mma_bf16(O[np * 2 + hf], pl, vb_h[np][hf * 2], vb_h[np][hf * 2 + 1]);
            #pragma unroll
            for (int np = 0; np < 4; np++)
                #pragma unroll
                for (int hf = 0; hf < 2; hf++)
                    mma_bf16(O[np * 2 + hf], ph, vb_l[np][hf * 2], vb_l[np][hf * 2 + 1]);
        }
        __syncthreads();
    }

    l0 += __shfl_xor_sync(0xffffffffu, l0, 1);
    l0 += __shfl_xor_sync(0xffffffffu, l0, 2);
    l1 += __shfl_xor_sync(0xffffffffu, l1, 1);
    l1 += __shfl_xor_sync(0xffffffffu, l1, 2);
    int r0 = q0 + wid * 16 + (lane >> 2);
    int r1 = r0 + 8;
    float f0 = (mk[r0] ? 1.0f : 0.0f) / l0;
    float f1 = (mk[r1] ? 1.0f : 0.0f) / l1;
    size_t gm0 = (size_t)(b * S_ + r0) * D_;
    size_t gm1 = (size_t)(b * S_ + r1) * D_;
    #pragma unroll
    for (int nf = 0; nf < 8; nf++) {
        int col = h * DH_ + nf * 8 + (lane & 3) * 2;
        float x0 = O[nf][0] * f0, y0 = O[nf][1] * f0;
        float x1 = O[nf][2] * f1, y1 = O[nf][3] * f1;
        uint32_t h0 = pack_bf16(x0, y0), h1 = pack_bf16(x1, y1);
        __nv_bfloat162 hh0 = *(__nv_bfloat162*)&h0;
        __nv_bfloat162 hh1 = *(__nv_bfloat162*)&h1;
        uint32_t lo0 = pack_bf16(x0 - __bfloat162float(hh0.x), y0 - __bfloat162float(hh0.y));
        uint32_t lo1 = pack_bf16(x1 - __bfloat162float(hh1.x), y1 - __bfloat162float(hh1.y));
        *(uint32_t*)&g_chi[gm0 + col] = h0;
        *(uint32_t*)&g_clo[gm0 + col] = lo0;
        *(uint32_t*)&g_chi[gm1 + col] = h1;
        *(uint32_t*)&g_clo[gm1 + col] = lo1;
    }
}

// ---------------- launch ----------------
extern "C" void kernel_launch(void* const* d_in, const int* in_sizes, int n_in,
                              void* d_out, int out_size) {
    (void)in_sizes; (void)n_in; (void)out_size;
    const float* X  = (const float*)d_in[0];
    const unsigned char* mask = (const unsigned char*)d_in[1];
    const float* Wq = (const float*)d_in[2];
    const float* bq = (const float*)d_in[3];
    const float* Wk = (const float*)d_in[4];
    const float* bk = (const float*)d_in[5];
    const float* Wv = (const float*)d_in[6];
    const float* bv = (const float*)d_in[7];
    const float* Wo = (const float*)d_in[8];
    const float* bo = (const float*)d_in[9];
    float* out = (float*)d_out;

    cudaFuncSetAttribute(mm_bf16x3, cudaFuncAttributeMaxDynamicSharedMemorySize, MM_SMEM);
    cudaFuncSetAttribute(flash_kernel, cudaFuncAttributeMaxDynamicSharedMemorySize, FL_SMEM);

    __nv_bfloat16 *xhi, *xlo, *chi, *clo;
    cudaGetSymbolAddress((void**)&xhi, g_xhi);
    cudaGetSymbolAddress((void**)&xlo, g_xlo);
    cudaGetSymbolAddress((void**)&chi, g_chi);
    cudaGetSymbolAddress((void**)&clo, g_clo);

    mask_prep_kernel<<<1, 256>>>(mask);
    wsplit_kernel<<<dim3(32, 32, 4), dim3(32, 8)>>>(Wq, Wk, Wv, Wo);
    bias_kernel<<<16, 256>>>(bq, bk, bv, bo);
    split_kernel<<<2048, 256>>>(X, xhi, xlo, M_TOT * D_ / 4);
    mm_bf16x3<<<dim3(24, 64), 256, MM_SMEM>>>(xhi, xlo, 0, 0, nullptr);

    flash_kernel<<<dim3(S_ / 128, BH_), 256, FL_SMEM>>>();

    mm_bf16x3<<<dim3(8, 64), 256, MM_SMEM>>>(chi, clo, 3072, 1, out);
}